// round 4
// baseline (speedup 1.0000x reference)
#include <cuda_runtime.h>
#include <cfloat>

// Problem constants
#define BBATCH 1024
#define NA     16     // agents n
#define MI     16     // items m
#define MENU   256
#define KTOT   257    // MENU + null option
#define NM     256    // NA*MI
#define PAWS   17     // padded row stride for per-agent-welfare

// Output layout: concatenation of the reference's 6 returned arrays (all f32)
#define OFF_CHOICE 0                                    // [B,KTOT]
#define OFF_ITEM   (OFF_CHOICE + (size_t)BBATCH*KTOT)   // [B,NA,MI]
#define OFF_UTIL   (OFF_ITEM   + (size_t)BBATCH*NM)     // [NA,B]
#define OFF_PAY    (OFF_UTIL   + (size_t)NA*BBATCH)     // [NA,B]
#define OFF_ALLOCP (OFF_PAY    + (size_t)NA*BBATCH)     // [B,KTOT,NA,MI]
#define OFF_BREV   (OFF_ALLOCP + (size_t)BBATCH*KTOT*NM)// [NA,B]

__global__ __launch_bounds__(256, 4)
void ramanet_kernel(const float* __restrict__ bids,
                    const float* __restrict__ values,
                    const float* __restrict__ allocs,
                    const float* __restrict__ wv,
                    const float* __restrict__ bv,
                    const int*   __restrict__ temp_ptr,
                    float* __restrict__ out)
{
    const int b    = blockIdx.x;
    const int tid  = threadIdx.x;
    const int warp = tid >> 5;
    const int lane = tid & 31;

    // decode softmax_temp robustly (int32 500 or float32 500.0f bit pattern)
    int ti = *temp_ptr;
    float temp = (ti >= 1 && ti <= 10000000) ? (float)ti : __int_as_float(ti);

    __shared__ float4 vb4_s[NM / 4];         // value - bid, as float4
    __shared__ float  w_s[NA];
    __shared__ float  bp_s[KTOT];
    __shared__ float  paw_s[KTOT * PAWS];
    __shared__ float  tw_s[KTOT];
    __shared__ float  choice_s[KTOT];
    __shared__ float  item_s[NM];
    __shared__ float  red_s[8];
    __shared__ float  red3_s[24];
    __shared__ float  bc_s[4];               // invSum, chosen_sum, alloc_b / maxv
    __shared__ float  rcs_s[NA], rb_s[NA];

    // ---- stage small per-batch data ----
    {
        size_t base = (size_t)b * NM;
        float vb = values[base + tid] - bids[base + tid];
        ((float*)vb4_s)[tid] = vb;
        item_s[tid] = 0.f;
        bp_s[tid]   = bv[(size_t)b * MENU + tid];
        if (tid < NA) w_s[tid] = wv[(size_t)b * NA + tid];
        if (tid == 0) bp_s[MENU] = 0.f;
    }
    __syncthreads();

    // Lane-constant agent weights: float4 lane covers 4 m's of agent n.
    // j=0 -> n = lane/4 (0..7); j=1 -> n = 8 + lane/4.
    const float wl0 = w_s[lane >> 2];
    const float wl1 = w_s[8 + (lane >> 2)];

    // ---- SINGLE PASS over allocs: copy-out + per_agent_welfare + total_welfare
    //      + online-softmax weighted accumulation of item_allocation ----
    const float4* abase4 = (const float4*)(allocs + (size_t)b * MENU * NM);
    float4*       outP4  = (float4*)(out + OFF_ALLOCP + (size_t)b * KTOT * NM);

    float  Mw = -FLT_MAX;                         // per-warp running max (lane-uniform)
    float4 A0 = make_float4(0.f, 0.f, 0.f, 0.f);  // running Σ e^{l-Mw} * allocs
    float4 A1 = make_float4(0.f, 0.f, 0.f, 0.f);

    const float4 vb0 = vb4_s[lane];
    const float4 vb1 = vb4_s[32 + lane];

    for (int k = warp; k < MENU; k += 8) {
        const float4* p = abase4 + (size_t)k * (NM / 4);
        float4*       q = outP4  + (size_t)k * (NM / 4);
        float4 v0 = __ldcs(&p[lane]);
        float4 v1 = __ldcs(&p[32 + lane]);
        __stcs(&q[lane], v0);
        __stcs(&q[32 + lane], v1);

        // per-lane weighted partial dot: w[n] * Σ_{4 m} a*vb
        float t0 = (v0.x * vb0.x + v0.y * vb0.y + v0.z * vb0.z + v0.w * vb0.w) * wl0;
        float t1 = (v1.x * vb1.x + v1.y * vb1.y + v1.z * vb1.z + v1.w * vb1.w) * wl1;
        // reduce over the 4 lanes of each agent -> paw[k][n]
        float g0 = t0 + __shfl_xor_sync(0xffffffffu, t0, 2);
        g0 += __shfl_xor_sync(0xffffffffu, g0, 1);
        float g1 = t1 + __shfl_xor_sync(0xffffffffu, t1, 2);
        g1 += __shfl_xor_sync(0xffffffffu, g1, 1);
        if ((lane & 3) == 0) {
            int n0 = lane >> 2;
            paw_s[k * PAWS + n0]     = g0;
            paw_s[k * PAWS + 8 + n0] = g1;
        }
        // total welfare: sum the 8 agent-groups (values replicated within groups of 4)
        float t = g0 + g1;
        t += __shfl_xor_sync(0xffffffffu, t, 4);
        t += __shfl_xor_sync(0xffffffffu, t, 8);
        t += __shfl_xor_sync(0xffffffffu, t, 16);
        if (lane == 0) tw_s[k] = t;

        // online-softmax accumulate: A = A*exp(Mw-Mn) + exp(l-Mn)*v
        float l  = (t + bp_s[k]) * temp;          // lane-uniform
        float Mn = fmaxf(Mw, l);
        float sc = __expf(Mw - l) ;               // note: if l<=Mw this is >=1 — wrong; use Mn
        sc = __expf(Mw - Mn);
        float cf = __expf(l - Mn);
        Mw = Mn;
        A0.x = A0.x * sc + cf * v0.x;  A0.y = A0.y * sc + cf * v0.y;
        A0.z = A0.z * sc + cf * v0.z;  A0.w = A0.w * sc + cf * v0.w;
        A1.x = A1.x * sc + cf * v1.x;  A1.y = A1.y * sc + cf * v1.y;
        A1.z = A1.z * sc + cf * v1.z;  A1.w = A1.w * sc + cf * v1.w;
    }
    // null allocation row = zeros (64 float4; 256 threads cover it 4x redundantly)
    __stcs(&((float4*)((float*)outP4 + (size_t)MENU * NM))[tid & 63],
           make_float4(0.f, 0.f, 0.f, 0.f));
    if (tid < NA) paw_s[MENU * PAWS + tid] = 0.f;   // null option
    if (tid == 0) tw_s[MENU] = 0.f;
    __syncthreads();

    // ---- main softmax over K=257 logits = (tw + bp)*temp ----
    float l0 = (tw_s[tid] + bp_s[tid]) * temp;       // k = tid
    {
        float mx = l0;
        if (tid == 0) mx = fmaxf(mx, 0.f);           // k=256 null logit = 0
        #pragma unroll
        for (int o = 16; o; o >>= 1) mx = fmaxf(mx, __shfl_xor_sync(0xffffffffu, mx, o));
        if (lane == 0) red_s[warp] = mx;
        __syncthreads();
        if (warp == 0) {
            float v = (lane < 8) ? red_s[lane] : -3.4e38f;
            #pragma unroll
            for (int o = 4; o; o >>= 1) v = fmaxf(v, __shfl_xor_sync(0xffffffffu, v, o));
            if (lane == 0) bc_s[3] = v;
        }
        __syncthreads();
    }
    const float maxv = bc_s[3];
    float e0 = __expf(l0 - maxv);
    choice_s[tid] = e0;
    float eNull = 0.f;
    if (tid == 0) { eNull = __expf(0.f - maxv); choice_s[MENU] = eNull; }

    // triple block sum: (Σe, Σe*tw, Σe*bp)
    {
        float s0 = e0 + eNull;                       // null adds e; its tw=bp=0
        float s1 = e0 * tw_s[tid];
        float s2 = e0 * bp_s[tid];
        #pragma unroll
        for (int o = 16; o; o >>= 1) {
            s0 += __shfl_xor_sync(0xffffffffu, s0, o);
            s1 += __shfl_xor_sync(0xffffffffu, s1, o);
            s2 += __shfl_xor_sync(0xffffffffu, s2, o);
        }
        if (lane == 0) { red3_s[warp] = s0; red3_s[8+warp] = s1; red3_s[16+warp] = s2; }
        __syncthreads();
        if (warp == 0) {
            float a = (lane < 8) ? red3_s[lane]     : 0.f;
            float c = (lane < 8) ? red3_s[8+lane]   : 0.f;
            float d = (lane < 8) ? red3_s[16+lane]  : 0.f;
            #pragma unroll
            for (int o = 4; o; o >>= 1) {
                a += __shfl_xor_sync(0xffffffffu, a, o);
                c += __shfl_xor_sync(0xffffffffu, c, o);
                d += __shfl_xor_sync(0xffffffffu, d, o);
            }
            if (lane == 0) {
                float inv = 1.f / a;
                bc_s[0] = inv;
                bc_s[1] = c * inv;   // chosen_sum
                bc_s[2] = d * inv;   // alloc_b
            }
        }
        __syncthreads();
    }
    const float invSum = bc_s[0];
    // normalize + write alloc_choice
    {
        float c = choice_s[tid] * invSum;
        out[OFF_CHOICE + (size_t)b * KTOT + tid] = c;
        if (tid == 0)
            out[OFF_CHOICE + (size_t)b * KTOT + MENU] = choice_s[MENU] * invSum;
    }

    // ---- merge per-warp online accumulators into item_allocation ----
    {
        float r = __expf(Mw - maxv) * invSum;        // lane-uniform per warp
        int base0 = lane * 4, base1 = (32 + lane) * 4;
        atomicAdd(&item_s[base0 + 0], A0.x * r);
        atomicAdd(&item_s[base0 + 1], A0.y * r);
        atomicAdd(&item_s[base0 + 2], A0.z * r);
        atomicAdd(&item_s[base0 + 3], A0.w * r);
        atomicAdd(&item_s[base1 + 0], A1.x * r);
        atomicAdd(&item_s[base1 + 1], A1.y * r);
        atomicAdd(&item_s[base1 + 2], A1.z * r);
        atomicAdd(&item_s[base1 + 3], A1.w * r);
    }

    // ---- counterfactual softmaxes: warp handles agents i = warp, warp+8 ----
    for (int i = warp; i < NA; i += 8) {
        float mx = -3.4e38f;
        for (int k = lane; k < KTOT; k += 32) {
            float l = (tw_s[k] - paw_s[k * PAWS + i] + bp_s[k]) * temp;
            mx = fmaxf(mx, l);
        }
        #pragma unroll
        for (int o = 16; o; o >>= 1) mx = fmaxf(mx, __shfl_xor_sync(0xffffffffu, mx, o));
        float s0 = 0.f, s1 = 0.f, s2 = 0.f;
        for (int k = lane; k < KTOT; k += 32) {
            float trm = tw_s[k] - paw_s[k * PAWS + i];
            float bp  = bp_s[k];
            float e   = __expf((trm + bp) * temp - mx);
            s0 += e; s1 += e * trm; s2 += e * bp;
        }
        #pragma unroll
        for (int o = 16; o; o >>= 1) {
            s0 += __shfl_xor_sync(0xffffffffu, s0, o);
            s1 += __shfl_xor_sync(0xffffffffu, s1, o);
            s2 += __shfl_xor_sync(0xffffffffu, s2, o);
        }
        if (lane == 0) { rcs_s[i] = s1 / s0; rb_s[i] = s2 / s0; }
    }
    __syncthreads();   // item_s atomics + rcs/rb ready

    // ---- item_allocation out + payments / utility / bid_rev ----
    out[OFF_ITEM + (size_t)b * NM + tid] = item_s[tid];
    if (tid < NA) {
        float br = 0.f, val = 0.f;
        size_t base = (size_t)b * NM + (size_t)tid * MI;
        #pragma unroll
        for (int m = 0; m < MI; ++m) {
            float it = item_s[tid * MI + m];
            br  += it * bids[base + m];
            val += it * values[base + m];
        }
        float pay = (bc_s[1] + bc_s[2] - rcs_s[tid] - rb_s[tid]) / w_s[tid] + br;
        out[OFF_UTIL + (size_t)tid * BBATCH + b] = val - pay;
        out[OFF_PAY  + (size_t)tid * BBATCH + b] = pay;
        out[OFF_BREV + (size_t)tid * BBATCH + b] = br;
    }
}

extern "C" void kernel_launch(void* const* d_in, const int* in_sizes, int n_in,
                              void* d_out, int out_size)
{
    const float* bids   = (const float*)d_in[0];
    const float* values = (const float*)d_in[1];
    const float* allocs = (const float*)d_in[2];
    const float* w      = (const float*)d_in[3];
    const float* b      = (const float*)d_in[4];
    const int*   temp   = (const int*)  d_in[5];
    float* out = (float*)d_out;

    ramanet_kernel<<<BBATCH, 256>>>(bids, values, allocs, w, b, temp, out);
}

// round 5
// speedup vs baseline: 1.0858x; 1.0858x over previous
#include <cuda_runtime.h>
#include <cfloat>

// Problem constants
#define BBATCH 1024
#define NA     16     // agents n
#define MI     16     // items m
#define MENU   256
#define KTOT   257    // MENU + null option
#define NM     256    // NA*MI
#define PAWS   17     // padded row stride for per-agent-welfare

// Output layout: concatenation of the reference's 6 returned arrays (all f32)
#define OFF_CHOICE 0                                    // [B,KTOT]
#define OFF_ITEM   (OFF_CHOICE + (size_t)BBATCH*KTOT)   // [B,NA,MI]
#define OFF_UTIL   (OFF_ITEM   + (size_t)BBATCH*NM)     // [NA,B]
#define OFF_PAY    (OFF_UTIL   + (size_t)NA*BBATCH)     // [NA,B]
#define OFF_ALLOCP (OFF_PAY    + (size_t)NA*BBATCH)     // [B,KTOT,NA,MI]
#define OFF_BREV   (OFF_ALLOCP + (size_t)BBATCH*KTOT*NM)// [NA,B]

__device__ __forceinline__ float dot4(float4 a, float4 b) {
    return a.x * b.x + a.y * b.y + a.z * b.z + a.w * b.w;
}

__global__ __launch_bounds__(256, 4)
void ramanet_kernel(const float* __restrict__ bids,
                    const float* __restrict__ values,
                    const float* __restrict__ allocs,
                    const float* __restrict__ wv,
                    const float* __restrict__ bv,
                    const int*   __restrict__ temp_ptr,
                    float* __restrict__ out)
{
    const int b    = blockIdx.x;
    const int tid  = threadIdx.x;
    const int warp = tid >> 5;
    const int lane = tid & 31;

    // decode softmax_temp robustly (int32 500 or float32 500.0f bit pattern)
    int ti = *temp_ptr;
    float temp = (ti >= 1 && ti <= 10000000) ? (float)ti : __int_as_float(ti);

    __shared__ float4 wvb4_s[NM / 4];        // w[n] * (value - bid), as float4
    __shared__ float  w_s[NA];
    __shared__ float  bp_s[KTOT];
    __shared__ float  paw_s[KTOT * PAWS];
    __shared__ float  tw_s[KTOT];
    __shared__ float  choice_s[KTOT];
    __shared__ float  item_s[NM];
    __shared__ float  red_s[8];
    __shared__ float  red3_s[24];
    __shared__ float  bc_s[4];               // invSum, chosen_sum, alloc_b, maxv
    __shared__ float  rcs_s[NA], rb_s[NA];

    // ---- stage small per-batch data ----
    {
        size_t base = (size_t)b * NM;
        if (tid < NA) w_s[tid] = wv[(size_t)b * NA + tid];
        __syncthreads();   // w_s ready before folding into wvb
        float vb = values[base + tid] - bids[base + tid];
        ((float*)wvb4_s)[tid] = vb * w_s[tid >> 4];   // fold w[n] in (n = tid/16)
        item_s[tid] = 0.f;
        bp_s[tid]   = bv[(size_t)b * MENU + tid];
        if (tid == 0) bp_s[MENU] = 0.f;
    }
    __syncthreads();

    // ---- SINGLE PASS over allocs (unrolled x2): copy-out + per_agent_welfare
    //      + total_welfare + online-softmax accumulation of item_allocation ----
    const float4* abase4 = (const float4*)(allocs + (size_t)b * MENU * NM);
    float4*       outP4  = (float4*)(out + OFF_ALLOCP + (size_t)b * KTOT * NM);

    float  Mw = -FLT_MAX;                         // per-warp running max (lane-uniform)
    float4 A0 = make_float4(0.f, 0.f, 0.f, 0.f);  // running Σ e^{l-Mw} * allocs
    float4 A1 = make_float4(0.f, 0.f, 0.f, 0.f);

    const float4 wvb0 = wvb4_s[lane];             // covers agent n = lane/4
    const float4 wvb1 = wvb4_s[32 + lane];        // covers agent n = 8 + lane/4

    for (int k = warp; k < MENU; k += 16) {
        // k_a = k (this warp), k_b = k + 8
        const float4* pa = abase4 + (size_t)k * (NM / 4);
        const float4* pb = pa + 8 * (NM / 4);
        // 4 independent 128-bit loads in flight
        float4 va0 = __ldcs(&pa[lane]);
        float4 va1 = __ldcs(&pa[32 + lane]);
        float4 vc0 = __ldcs(&pb[lane]);
        float4 vc1 = __ldcs(&pb[32 + lane]);
        float4* qa = outP4 + (size_t)k * (NM / 4);
        float4* qb = qa + 8 * (NM / 4);
        __stcs(&qa[lane],      va0);
        __stcs(&qa[32 + lane], va1);
        __stcs(&qb[lane],      vc0);
        __stcs(&qb[32 + lane], vc1);

        // weighted partial dots (w folded into wvb)
        float ta0 = dot4(va0, wvb0);
        float ta1 = dot4(va1, wvb1);
        float tb0 = dot4(vc0, wvb0);
        float tb1 = dot4(vc1, wvb1);
        // butterfly over the 4 lanes of each agent group
        ta0 += __shfl_xor_sync(0xffffffffu, ta0, 2);
        ta1 += __shfl_xor_sync(0xffffffffu, ta1, 2);
        tb0 += __shfl_xor_sync(0xffffffffu, tb0, 2);
        tb1 += __shfl_xor_sync(0xffffffffu, tb1, 2);
        ta0 += __shfl_xor_sync(0xffffffffu, ta0, 1);
        ta1 += __shfl_xor_sync(0xffffffffu, ta1, 1);
        tb0 += __shfl_xor_sync(0xffffffffu, tb0, 1);
        tb1 += __shfl_xor_sync(0xffffffffu, tb1, 1);
        if ((lane & 3) == 0) {
            int n0 = lane >> 2;
            paw_s[k * PAWS + n0]            = ta0;
            paw_s[k * PAWS + 8 + n0]        = ta1;
            paw_s[(k + 8) * PAWS + n0]      = tb0;
            paw_s[(k + 8) * PAWS + 8 + n0]  = tb1;
        }
        // total welfare: butterfly over the 8 agent groups
        float sa = ta0 + ta1;
        float sb = tb0 + tb1;
        sa += __shfl_xor_sync(0xffffffffu, sa, 4);
        sb += __shfl_xor_sync(0xffffffffu, sb, 4);
        sa += __shfl_xor_sync(0xffffffffu, sa, 8);
        sb += __shfl_xor_sync(0xffffffffu, sb, 8);
        sa += __shfl_xor_sync(0xffffffffu, sa, 16);
        sb += __shfl_xor_sync(0xffffffffu, sb, 16);
        if (lane == 0) { tw_s[k] = sa; tw_s[k + 8] = sb; }

        // combined online-softmax update for both k's (one rescale, 3 exps)
        float la = (sa + bp_s[k]) * temp;
        float lb = (sb + bp_s[k + 8]) * temp;
        float Mn = fmaxf(Mw, fmaxf(la, lb));
        float sc = __expf(Mw - Mn);
        float ca = __expf(la - Mn);
        float cb = __expf(lb - Mn);
        Mw = Mn;
        A0.x = A0.x * sc + ca * va0.x + cb * vc0.x;
        A0.y = A0.y * sc + ca * va0.y + cb * vc0.y;
        A0.z = A0.z * sc + ca * va0.z + cb * vc0.z;
        A0.w = A0.w * sc + ca * va0.w + cb * vc0.w;
        A1.x = A1.x * sc + ca * va1.x + cb * vc1.x;
        A1.y = A1.y * sc + ca * va1.y + cb * vc1.y;
        A1.z = A1.z * sc + ca * va1.z + cb * vc1.z;
        A1.w = A1.w * sc + ca * va1.w + cb * vc1.w;
    }
    // null allocation row = zeros (64 float4)
    if (tid < 64)
        __stcs(&((float4*)((float*)outP4 + (size_t)MENU * NM))[tid],
               make_float4(0.f, 0.f, 0.f, 0.f));
    if (tid < NA) paw_s[MENU * PAWS + tid] = 0.f;   // null option
    if (tid == 0) tw_s[MENU] = 0.f;
    __syncthreads();

    // ---- main softmax over K=257 logits = (tw + bp)*temp ----
    float l0 = (tw_s[tid] + bp_s[tid]) * temp;       // k = tid
    {
        float mx = l0;
        if (tid == 0) mx = fmaxf(mx, 0.f);           // k=256 null logit = 0
        #pragma unroll
        for (int o = 16; o; o >>= 1) mx = fmaxf(mx, __shfl_xor_sync(0xffffffffu, mx, o));
        if (lane == 0) red_s[warp] = mx;
        __syncthreads();
        if (warp == 0) {
            float v = (lane < 8) ? red_s[lane] : -3.4e38f;
            #pragma unroll
            for (int o = 4; o; o >>= 1) v = fmaxf(v, __shfl_xor_sync(0xffffffffu, v, o));
            if (lane == 0) bc_s[3] = v;
        }
        __syncthreads();
    }
    const float maxv = bc_s[3];
    float e0 = __expf(l0 - maxv);
    choice_s[tid] = e0;
    float eNull = 0.f;
    if (tid == 0) { eNull = __expf(0.f - maxv); choice_s[MENU] = eNull; }

    // triple block sum: (Σe, Σe*tw, Σe*bp)
    {
        float s0 = e0 + eNull;                       // null adds e; its tw=bp=0
        float s1 = e0 * tw_s[tid];
        float s2 = e0 * bp_s[tid];
        #pragma unroll
        for (int o = 16; o; o >>= 1) {
            s0 += __shfl_xor_sync(0xffffffffu, s0, o);
            s1 += __shfl_xor_sync(0xffffffffu, s1, o);
            s2 += __shfl_xor_sync(0xffffffffu, s2, o);
        }
        if (lane == 0) { red3_s[warp] = s0; red3_s[8+warp] = s1; red3_s[16+warp] = s2; }
        __syncthreads();
        if (warp == 0) {
            float a = (lane < 8) ? red3_s[lane]     : 0.f;
            float c = (lane < 8) ? red3_s[8+lane]   : 0.f;
            float d = (lane < 8) ? red3_s[16+lane]  : 0.f;
            #pragma unroll
            for (int o = 4; o; o >>= 1) {
                a += __shfl_xor_sync(0xffffffffu, a, o);
                c += __shfl_xor_sync(0xffffffffu, c, o);
                d += __shfl_xor_sync(0xffffffffu, d, o);
            }
            if (lane == 0) {
                float inv = 1.f / a;
                bc_s[0] = inv;
                bc_s[1] = c * inv;   // chosen_sum
                bc_s[2] = d * inv;   // alloc_b
            }
        }
        __syncthreads();
    }
    const float invSum = bc_s[0];
    // write alloc_choice
    {
        out[OFF_CHOICE + (size_t)b * KTOT + tid] = choice_s[tid] * invSum;
        if (tid == 0)
            out[OFF_CHOICE + (size_t)b * KTOT + MENU] = choice_s[MENU] * invSum;
    }

    // ---- merge per-warp online accumulators into item_allocation ----
    {
        float r = __expf(Mw - maxv) * invSum;        // lane-uniform per warp
        int base0 = lane * 4, base1 = (32 + lane) * 4;
        atomicAdd(&item_s[base0 + 0], A0.x * r);
        atomicAdd(&item_s[base0 + 1], A0.y * r);
        atomicAdd(&item_s[base0 + 2], A0.z * r);
        atomicAdd(&item_s[base0 + 3], A0.w * r);
        atomicAdd(&item_s[base1 + 0], A1.x * r);
        atomicAdd(&item_s[base1 + 1], A1.y * r);
        atomicAdd(&item_s[base1 + 2], A1.z * r);
        atomicAdd(&item_s[base1 + 3], A1.w * r);
    }

    // ---- counterfactual softmaxes: warp handles agents i = warp, warp+8 ----
    for (int i = warp; i < NA; i += 8) {
        float mx = -3.4e38f;
        for (int k = lane; k < KTOT; k += 32) {
            float l = (tw_s[k] - paw_s[k * PAWS + i] + bp_s[k]) * temp;
            mx = fmaxf(mx, l);
        }
        #pragma unroll
        for (int o = 16; o; o >>= 1) mx = fmaxf(mx, __shfl_xor_sync(0xffffffffu, mx, o));
        float s0 = 0.f, s1 = 0.f, s2 = 0.f;
        for (int k = lane; k < KTOT; k += 32) {
            float trm = tw_s[k] - paw_s[k * PAWS + i];
            float bp  = bp_s[k];
            float e   = __expf((trm + bp) * temp - mx);
            s0 += e; s1 += e * trm; s2 += e * bp;
        }
        #pragma unroll
        for (int o = 16; o; o >>= 1) {
            s0 += __shfl_xor_sync(0xffffffffu, s0, o);
            s1 += __shfl_xor_sync(0xffffffffu, s1, o);
            s2 += __shfl_xor_sync(0xffffffffu, s2, o);
        }
        if (lane == 0) { rcs_s[i] = s1 / s0; rb_s[i] = s2 / s0; }
    }
    __syncthreads();   // item_s atomics + rcs/rb ready

    // ---- item_allocation out + payments / utility / bid_rev ----
    out[OFF_ITEM + (size_t)b * NM + tid] = item_s[tid];
    if (tid < NA) {
        float br = 0.f, val = 0.f;
        size_t base = (size_t)b * NM + (size_t)tid * MI;
        #pragma unroll
        for (int m = 0; m < MI; ++m) {
            float it = item_s[tid * MI + m];
            br  += it * bids[base + m];
            val += it * values[base + m];
        }
        float pay = (bc_s[1] + bc_s[2] - rcs_s[tid] - rb_s[tid]) / w_s[tid] + br;
        out[OFF_UTIL + (size_t)tid * BBATCH + b] = val - pay;
        out[OFF_PAY  + (size_t)tid * BBATCH + b] = pay;
        out[OFF_BREV + (size_t)tid * BBATCH + b] = br;
    }
}

extern "C" void kernel_launch(void* const* d_in, const int* in_sizes, int n_in,
                              void* d_out, int out_size)
{
    const float* bids   = (const float*)d_in[0];
    const float* values = (const float*)d_in[1];
    const float* allocs = (const float*)d_in[2];
    const float* w      = (const float*)d_in[3];
    const float* b      = (const float*)d_in[4];
    const int*   temp   = (const int*)  d_in[5];
    float* out = (float*)d_out;

    ramanet_kernel<<<BBATCH, 256>>>(bids, values, allocs, w, b, temp, out);
}